// round 2
// baseline (speedup 1.0000x reference)
#include <cuda_runtime.h>
#include <cuda_bf16.h>
#include <cstdint>

// Problem constants
#define BB 32
#define SS 512
#define DD 1024
#define HH 1024
#define OO 1024
#define LL 2

// ---------------------------------------------------------------------------
// Scratch (device globals -- allocation-free per harness rules)
// All per-timestep activations stored TRANSPOSED: [n][b] (b fastest, 32 wide)
// ---------------------------------------------------------------------------
__device__ float g_X0[SS * 3 * HH * BB];   // [t][gate][n][b]  (layer0 x-parts + bias)
__device__ float g_Y [SS * HH * BB];       // [t][n][b]        (layer1 outputs)
__device__ float g_h0[2][HH * BB];         // double-buffered states, [n][b]
__device__ float g_h1[2][HH * BB];
__device__ float g_z0[HH * BB], g_r0[HH * BB];
__device__ float g_p1z[HH * BB], g_p1r[HH * BB];
__device__ float g_z1[HH * BB], g_r1[HH * BB], g_pg1[HH * BB];
__device__ unsigned g_bar_count;
__device__ unsigned g_bar_gen;

// ---------------------------------------------------------------------------
// Helpers
// ---------------------------------------------------------------------------
__device__ __forceinline__ float sigmoidf_(float x) {
    return __fdividef(1.0f, 1.0f + __expf(-x));
}
__device__ __forceinline__ float tanhf_(float x) {
    return __fdividef(2.0f, 1.0f + __expf(-2.0f * x)) - 1.0f;
}

// Grid-wide barrier. Safe because grid is clamped to guaranteed-resident size.
__device__ __forceinline__ void gridbar(int nctas) {
    __syncthreads();
    if (threadIdx.x == 0) {
        __threadfence();  // release (gpu scope -> CCTL.IVALL on sm_10x)
        unsigned gen = *(volatile unsigned*)&g_bar_gen;
        unsigned a = atomicAdd(&g_bar_count, 1u);
        if (a == (unsigned)nctas - 1u) {
            g_bar_count = 0u;
            __threadfence();
            atomicAdd(&g_bar_gen, 1u);
        } else {
            while (*(volatile unsigned*)&g_bar_gen == gen) { __nanosleep(32); }
        }
        __threadfence();  // acquire: invalidate L1 before consuming peers' writes
    }
    __syncthreads();
}

// Warp-cooperative M=32 GEMM tile: lane = b (0..31), computes NG outputs
// acc[j] = sum_k A[k][lane] (* M[k][lane]) * W[n0+j][k]
// A,M are transposed [K][32]; W is row-major [N][K]. W read streaming.
template<int NG, bool HASM>
__device__ __forceinline__ void warp_dot(
    const float* __restrict__ AT, const float* __restrict__ MT,
    const float* __restrict__ W, int n0, int lane, float* acc)
{
    const float* a_ptr = AT + lane;
    const float* m_ptr = HASM ? (MT + lane) : nullptr;
    #pragma unroll 2
    for (int k = 0; k < HH; k += 4) {
        float a0 = a_ptr[(k + 0) * BB];
        float a1 = a_ptr[(k + 1) * BB];
        float a2 = a_ptr[(k + 2) * BB];
        float a3 = a_ptr[(k + 3) * BB];
        if (HASM) {
            a0 *= m_ptr[(k + 0) * BB];
            a1 *= m_ptr[(k + 1) * BB];
            a2 *= m_ptr[(k + 2) * BB];
            a3 *= m_ptr[(k + 3) * BB];
        }
        #pragma unroll
        for (int j = 0; j < NG; ++j) {
            float4 w = __ldcs(reinterpret_cast<const float4*>(W + (size_t)(n0 + j) * HH + k));
            acc[j] = fmaf(a0, w.x, acc[j]);
            acc[j] = fmaf(a1, w.y, acc[j]);
            acc[j] = fmaf(a2, w.z, acc[j]);
            acc[j] = fmaf(a3, w.w, acc[j]);
        }
    }
}

// ---------------------------------------------------------------------------
// Kernel: init hidden states (transposed)
// ---------------------------------------------------------------------------
__global__ void init_states_kernel(const float* __restrict__ hs) {
    int idx = blockIdx.x * blockDim.x + threadIdx.x;  // 32*2*1024
    if (idx >= BB * LL * HH) return;
    int b = idx >> 11;
    int l = (idx >> 10) & 1;
    int h = idx & 1023;
    float v = hs[idx];  // hs is [b][l][h] contiguous == idx order
    if (l == 0) g_h0[0][h * BB + b] = v;
    else        g_h1[0][h * BB + b] = v;
}

// ---------------------------------------------------------------------------
// Kernel: big GEMM for layer-0 input projections (3 gates via blockIdx.z)
// C[(s,g,n,b)] = input[b,s,:] . Wx[g][0][n,:] + bias[g][0][n]
// input viewed as A[16384][1024], m = b*512 + s
// Tile 64x64, K-chunk 16, 256 threads, 4x4 per thread.
// ---------------------------------------------------------------------------
__global__ void __launch_bounds__(256) gemm_x0_kernel(
    const float* __restrict__ A,
    const float* __restrict__ Wz, const float* __restrict__ Wr, const float* __restrict__ Wg,
    const float* __restrict__ bz, const float* __restrict__ br, const float* __restrict__ bg)
{
    __shared__ float As[16][68];
    __shared__ float Bs[16][68];
    const int gate = blockIdx.z;
    const float* W    = (gate == 0) ? Wz : (gate == 1) ? Wr : Wg;
    const float* bias = (gate == 0) ? bz : (gate == 1) ? br : bg;
    const int n0 = blockIdx.x * 64;
    const int m0 = blockIdx.y * 64;
    const int tid = threadIdx.x;
    const int lr = tid >> 2;          // 0..63
    const int lk = (tid & 3) * 4;     // 0,4,8,12
    const int tm = tid >> 4;          // 0..15
    const int tn = tid & 15;          // 0..15

    float c[4][4] = {};
    for (int k0 = 0; k0 < DD; k0 += 16) {
        float4 av = *reinterpret_cast<const float4*>(A + (size_t)(m0 + lr) * DD + k0 + lk);
        float4 bv = *reinterpret_cast<const float4*>(W + (size_t)(n0 + lr) * DD + k0 + lk);
        As[lk + 0][lr] = av.x; As[lk + 1][lr] = av.y; As[lk + 2][lr] = av.z; As[lk + 3][lr] = av.w;
        Bs[lk + 0][lr] = bv.x; Bs[lk + 1][lr] = bv.y; Bs[lk + 2][lr] = bv.z; Bs[lk + 3][lr] = bv.w;
        __syncthreads();
        #pragma unroll
        for (int k = 0; k < 16; ++k) {
            float a[4], b4[4];
            #pragma unroll
            for (int i = 0; i < 4; ++i) a[i]  = As[k][tm * 4 + i];
            #pragma unroll
            for (int j = 0; j < 4; ++j) b4[j] = Bs[k][tn * 4 + j];
            #pragma unroll
            for (int i = 0; i < 4; ++i)
                #pragma unroll
                for (int j = 0; j < 4; ++j)
                    c[i][j] = fmaf(a[i], b4[j], c[i][j]);
        }
        __syncthreads();
    }
    #pragma unroll
    for (int i = 0; i < 4; ++i) {
        int m = m0 + tm * 4 + i;
        int b = m >> 9;       // m = b*512 + s
        int s = m & 511;
        #pragma unroll
        for (int j = 0; j < 4; ++j) {
            int n = n0 + tn * 4 + j;
            g_X0[(((size_t)s * 3 + gate) * HH + n) * BB + b] = c[i][j] + __ldg(&bias[n]);
        }
    }
}

// ---------------------------------------------------------------------------
// Kernel: persistent recurrent loop (grid = resident CTA count, 256 threads)
// 4 dependent phases per timestep, grid barrier between phases.
// ---------------------------------------------------------------------------
__global__ void __launch_bounds__(256) gru_recurrent_kernel(
    const float* __restrict__ Whz0, const float* __restrict__ Whr0, const float* __restrict__ Whg0,
    const float* __restrict__ Wxz1, const float* __restrict__ Whz1,
    const float* __restrict__ Wxr1, const float* __restrict__ Whr1,
    const float* __restrict__ Wxg1, const float* __restrict__ Whg1,
    const float* __restrict__ bz1, const float* __restrict__ br1, const float* __restrict__ bg1,
    int nctas)
{
    const int lane = threadIdx.x & 31;
    const int wid = blockIdx.x * (blockDim.x >> 5) + (threadIdx.x >> 5);
    const int nwarps = nctas * (blockDim.x >> 5);

    for (int t = 0; t < SS; ++t) {
        const int par = t & 1;
        const float* __restrict__ h0  = g_h0[par];
        const float* __restrict__ h1  = g_h1[par];
        float* __restrict__ h0n = g_h0[par ^ 1];
        float* __restrict__ h1n = g_h1[par ^ 1];
        const float* __restrict__ X0 = g_X0 + (size_t)t * (3 * HH * BB);

        // ---- phase 1: z0pre, r0pre (K=h0), p1z, p1r (K=h1). 4 GEMMs, NG=4.
        for (int task = wid; task < 1024; task += nwarps) {
            int gm = task >> 8;
            int n0 = (task & 255) * 4;
            const float* A = (gm < 2) ? h0 : h1;
            const float* W = (gm == 0) ? Whz0 : (gm == 1) ? Whr0 : (gm == 2) ? Whz1 : Whr1;
            float acc[4] = {0.f, 0.f, 0.f, 0.f};
            warp_dot<4, false>(A, nullptr, W, n0, lane, acc);
            #pragma unroll
            for (int j = 0; j < 4; ++j) {
                int n = n0 + j;
                int off = n * BB + lane;
                if (gm == 0)      g_z0[off] = sigmoidf_(acc[j] + X0[off]);
                else if (gm == 1) g_r0[off] = sigmoidf_(acc[j] + X0[HH * BB + off]);
                else if (gm == 2) g_p1z[off] = acc[j];
                else              g_p1r[off] = acc[j];
            }
        }
        gridbar(nctas);

        // ---- phase 2: g0 = tanh(X0g + (r0*h0) @ Whg0^T); h0' = z0*h0 + (1-z0)*g0
        for (int task = wid; task < 512; task += nwarps) {
            int n0 = task * 2;
            float acc[2] = {0.f, 0.f};
            warp_dot<2, true>(h0, g_r0, Whg0, n0, lane, acc);
            #pragma unroll
            for (int j = 0; j < 2; ++j) {
                int off = (n0 + j) * BB + lane;
                float gg = tanhf_(acc[j] + X0[2 * HH * BB + off]);
                float z = g_z0[off];
                float hp = h0[off];
                h0n[off] = z * hp + (1.0f - z) * gg;
            }
        }
        gridbar(nctas);

        // ---- phase 3: z1, r1, pg1 from h0' (x-parts of layer 1). 3 GEMMs, NG=4.
        for (int task = wid; task < 768; task += nwarps) {
            int gm = task >> 8;
            int n0 = (task & 255) * 4;
            const float* W = (gm == 0) ? Wxz1 : (gm == 1) ? Wxr1 : Wxg1;
            float acc[4] = {0.f, 0.f, 0.f, 0.f};
            warp_dot<4, false>(h0n, nullptr, W, n0, lane, acc);
            #pragma unroll
            for (int j = 0; j < 4; ++j) {
                int n = n0 + j;
                int off = n * BB + lane;
                if (gm == 0)      g_z1[off] = sigmoidf_(acc[j] + g_p1z[off] + __ldg(&bz1[n]));
                else if (gm == 1) g_r1[off] = sigmoidf_(acc[j] + g_p1r[off] + __ldg(&br1[n]));
                else              g_pg1[off] = acc[j] + __ldg(&bg1[n]);
            }
        }
        gridbar(nctas);

        // ---- phase 4: g1 = tanh(pg1 + (r1*h1) @ Whg1^T); h1' -> state + Y
        for (int task = wid; task < 512; task += nwarps) {
            int n0 = task * 2;
            float acc[2] = {0.f, 0.f};
            warp_dot<2, true>(h1, g_r1, Whg1, n0, lane, acc);
            #pragma unroll
            for (int j = 0; j < 2; ++j) {
                int off = (n0 + j) * BB + lane;
                float gg = tanhf_(acc[j] + g_pg1[off]);
                float z = g_z1[off];
                float hp = h1[off];
                float hn = z * hp + (1.0f - z) * gg;
                h1n[off] = hn;
                g_Y[(size_t)t * (HH * BB) + off] = hn;
            }
        }
        gridbar(nctas);
    }
}

// ---------------------------------------------------------------------------
// Kernel: output projection out[b][s][o] = Y[s][:,b] . Why[o][:] + by[o]
// A[m][k] = g_Y[s*32768 + k*32 + b], m = s*32 + b  (coalesced over b)
// ---------------------------------------------------------------------------
__global__ void __launch_bounds__(256) gemm_proj_kernel(
    const float* __restrict__ W, const float* __restrict__ bias, float* __restrict__ out)
{
    __shared__ float As[16][68];
    __shared__ float Bs[16][68];
    const int n0 = blockIdx.x * 64;
    const int m0 = blockIdx.y * 64;
    const int tid = threadIdx.x;
    const int kk = tid >> 4;           // 0..15 (k within chunk)
    const int m4 = (tid & 15) * 4;     // 0..60 (m within tile)
    const int lr = tid >> 2;
    const int lk = (tid & 3) * 4;
    const int tm = tid >> 4;
    const int tn = tid & 15;

    const int mA = m0 + m4;
    const int sA = mA >> 5;            // m = s*32 + b ; m4 % 4 == 0 so no 32-crossing
    const int bA = mA & 31;

    float c[4][4] = {};
    for (int k0 = 0; k0 < HH; k0 += 16) {
        float4 av = *reinterpret_cast<const float4*>(
            g_Y + (size_t)sA * (HH * BB) + (size_t)(k0 + kk) * BB + bA);
        float4 bv = *reinterpret_cast<const float4*>(W + (size_t)(n0 + lr) * HH + k0 + lk);
        As[kk][m4 + 0] = av.x; As[kk][m4 + 1] = av.y; As[kk][m4 + 2] = av.z; As[kk][m4 + 3] = av.w;
        Bs[lk + 0][lr] = bv.x; Bs[lk + 1][lr] = bv.y; Bs[lk + 2][lr] = bv.z; Bs[lk + 3][lr] = bv.w;
        __syncthreads();
        #pragma unroll
        for (int k = 0; k < 16; ++k) {
            float a[4], b4[4];
            #pragma unroll
            for (int i = 0; i < 4; ++i) a[i]  = As[k][tm * 4 + i];
            #pragma unroll
            for (int j = 0; j < 4; ++j) b4[j] = Bs[k][tn * 4 + j];
            #pragma unroll
            for (int i = 0; i < 4; ++i)
                #pragma unroll
                for (int j = 0; j < 4; ++j)
                    c[i][j] = fmaf(a[i], b4[j], c[i][j]);
        }
        __syncthreads();
    }
    #pragma unroll
    for (int i = 0; i < 4; ++i) {
        int m = m0 + tm * 4 + i;
        int s = m >> 5;
        int b = m & 31;
        #pragma unroll
        for (int j = 0; j < 4; ++j) {
            int n = n0 + tn * 4 + j;
            out[(size_t)b * (SS * OO) + (size_t)s * OO + n] = c[i][j] + __ldg(&bias[n]);
        }
    }
}

// ---------------------------------------------------------------------------
// Kernel: write final hidden states to d_out tail, [b][l][h]
// ---------------------------------------------------------------------------
__global__ void copy_hidden_kernel(float* __restrict__ outh) {
    int idx = blockIdx.x * blockDim.x + threadIdx.x;
    if (idx >= BB * LL * HH) return;
    int b = idx >> 11;
    int l = (idx >> 10) & 1;
    int h = idx & 1023;
    // after t=511, new states live in parity (511+1)&1 = 0
    outh[idx] = (l == 0) ? g_h0[0][h * BB + b] : g_h1[0][h * BB + b];
}

// ---------------------------------------------------------------------------
// Launch
// ---------------------------------------------------------------------------
extern "C" void kernel_launch(void* const* d_in, const int* in_sizes, int n_in,
                              void* d_out, int out_size) {
    const float* input  = (const float*)d_in[0];   // [B,S,D]
    const float* hidden = (const float*)d_in[1];   // [B,L,H]
    const float* Wxz = (const float*)d_in[2];      // [L,H,D]
    const float* Whz = (const float*)d_in[3];      // [L,H,H]
    const float* bz  = (const float*)d_in[4];      // [L,H]
    const float* Wxr = (const float*)d_in[5];
    const float* Whr = (const float*)d_in[6];
    const float* br  = (const float*)d_in[7];
    const float* Wxg = (const float*)d_in[8];
    const float* Whg = (const float*)d_in[9];
    const float* bg  = (const float*)d_in[10];
    const float* Why = (const float*)d_in[11];     // [O,H]
    const float* by  = (const float*)d_in[12];     // [O]
    float* out = (float*)d_out;

    int dev = 0;
    cudaGetDevice(&dev);
    int nsm = 0;
    cudaDeviceGetAttribute(&nsm, cudaDevAttrMultiProcessorCount, dev);
    if (nsm <= 0) nsm = 132;

    // Clamp grid to guaranteed-resident CTA count (grid barrier safety).
    int maxper = 1;
    cudaOccupancyMaxActiveBlocksPerMultiprocessor(&maxper, gru_recurrent_kernel, 256, 0);
    if (maxper < 1) maxper = 1;
    int nctas = nsm;  // 1 CTA/SM is the target; maxper>=1 guarantees residency

    // layer offsets
    const size_t WHD = (size_t)HH * DD;
    const size_t WHHo = (size_t)HH * HH;

    init_states_kernel<<<(BB * LL * HH + 255) / 256, 256>>>(hidden);

    gemm_x0_kernel<<<dim3(HH / 64, (BB * SS) / 64, 3), 256>>>(
        input, Wxz, Wxr, Wxg, bz, br, bg);

    gru_recurrent_kernel<<<nctas, 256>>>(
        Whz, Whr, Whg,
        Wxz + WHD, Whz + WHHo,
        Wxr + WHD, Whr + WHHo,
        Wxg + WHD, Whg + WHHo,
        bz + HH, br + HH, bg + HH,
        nctas);

    gemm_proj_kernel<<<dim3(OO / 64, (BB * SS) / 64), 256>>>(Why, by, out);

    copy_hidden_kernel<<<(BB * LL * HH + 255) / 256, 256>>>(out + (size_t)BB * SS * OO);
}

// round 5
// speedup vs baseline: 4.6299x; 4.6299x over previous
#include <cuda_runtime.h>
#include <cuda_bf16.h>
#include <cstdint>

// Problem constants
#define BB 32
#define SS 512
#define DD 1024
#define HH 1024
#define OO 1024
#define LL 2

// ---------------------------------------------------------------------------
// Scratch (device globals -- allocation-free per harness rules)
// All per-timestep activations stored TRANSPOSED: [n][b] (b fastest, 32 wide)
// ---------------------------------------------------------------------------
__device__ float g_X0[SS * 3 * HH * BB];   // [t][gate][n][b]  (layer0 x-parts + bias)
__device__ float g_Y [SS * HH * BB];       // [t][n][b]        (layer1 outputs)
__device__ float g_h0[2][HH * BB];         // double-buffered states, [n][b]
__device__ float g_h1[2][HH * BB];
__device__ float g_z0[HH * BB], g_r0[HH * BB];
__device__ float g_hz1[HH * BB], g_hr1[HH * BB];   // layer1 h-part partials
__device__ float g_z1[HH * BB], g_r1[HH * BB], g_pg1[HH * BB];
__device__ unsigned g_bar_count;
__device__ unsigned g_bar_gen;

// ---------------------------------------------------------------------------
// Helpers
// ---------------------------------------------------------------------------
__device__ __forceinline__ float sigmoidf_(float x) {
    return __fdividef(1.0f, 1.0f + __expf(-x));
}
__device__ __forceinline__ float tanhf_(float x) {
    return __fdividef(2.0f, 1.0f + __expf(-2.0f * x)) - 1.0f;
}
__device__ __forceinline__ uint32_t sptr(const void* p) {
    return (uint32_t)__cvta_generic_to_shared(p);
}
#define CP_COMMIT() asm volatile("cp.async.commit_group;")
#define CP_WAIT0()  asm volatile("cp.async.wait_group 0;")
#define CP_WAIT1()  asm volatile("cp.async.wait_group 1;")

// Grid-wide barrier (1 CTA/SM guaranteed by 192KB smem footprint).
__device__ __forceinline__ void gridbar(int nctas) {
    __syncthreads();
    if (threadIdx.x == 0) {
        __threadfence();  // release
        unsigned gen = *(volatile unsigned*)&g_bar_gen;
        unsigned a = atomicAdd(&g_bar_count, 1u);
        if (a == (unsigned)nctas - 1u) {
            g_bar_count = 0u;
            __threadfence();
            atomicAdd(&g_bar_gen, 1u);
        } else {
            while (*(volatile unsigned*)&g_bar_gen == gen) { __nanosleep(32); }
        }
        __threadfence();  // acquire (L1 invalidate)
    }
    __syncthreads();
}

// ---------------------------------------------------------------------------
// cp.async staging
// ---------------------------------------------------------------------------
// Full activation [1024][32] (128 KB) -> sA. Commits its own group.
__device__ __forceinline__ void stageA(float* sA, const float* __restrict__ src, int tid) {
    #pragma unroll
    for (int i = 0; i < 32; ++i) {
        int u = tid + i * 256;
        uint32_t d = sptr(sA + (u << 2));
        asm volatile("cp.async.cg.shared.global [%0], [%1], 16;" :: "r"(d), "l"(src + (u << 2)));
    }
    CP_COMMIT();
}

// Weight chunk: TR rows x 256 K-floats from Wg rows [n0, n0+TR), K-chunk kc.
template<int TR>
__device__ __forceinline__ void issueW(float* dst, const float* __restrict__ Wg,
                                       int n0, int kc, int tid) {
    #pragma unroll
    for (int i = 0; i < TR / 4; ++i) {
        int u = tid + i * 256;            // 16B unit index, TR*64 total
        int row = u >> 6, c16 = u & 63;
        const float* src = Wg + ((size_t)(n0 + row) << 10) + (kc << 8) + (c16 << 2);
        uint32_t d = sptr(dst + (row << 8) + (c16 << 2));
        asm volatile("cp.async.cg.shared.global [%0], [%1], 16;" :: "r"(d), "l"(src));
    }
}

// ---------------------------------------------------------------------------
// One GEMM task: TR rows x 32 batch x K=1024, W streamed via 2-deep pipeline.
// Warp w owns rows [w*G, w*G+G), G = TR/8. acc[r] is per-lane (lane = batch).
// ---------------------------------------------------------------------------
template<int TR>
__device__ __forceinline__ void gemm_task(const float* sA, float* sW,
                                          const float* __restrict__ Wg, int n0,
                                          int tid, int wid, int lane, float* acc) {
    const int G = TR / 8;
    issueW<TR>(sW, Wg, n0, 0, tid);
    CP_COMMIT();
    #pragma unroll
    for (int r = 0; r < G; ++r) acc[r] = 0.0f;

    for (int c = 0; c < 4; ++c) {
        if (c < 3) {
            issueW<TR>(sW + ((c + 1) & 1) * 8192, Wg, n0, c + 1, tid);
            CP_COMMIT();
            CP_WAIT1();
        } else {
            CP_WAIT0();
        }
        __syncthreads();
        const float* Wb = sW + (c & 1) * 8192;
        const float* Ab = sA + (c << 13);            // c*256*32
        const float* wr = Wb + (wid * G) * 256;
        #pragma unroll 2
        for (int k = 0; k < 256; k += 4) {
            float a0 = Ab[((k + 0) << 5) + lane];
            float a1 = Ab[((k + 1) << 5) + lane];
            float a2 = Ab[((k + 2) << 5) + lane];
            float a3 = Ab[((k + 3) << 5) + lane];
            #pragma unroll
            for (int r = 0; r < G; ++r) {
                float4 w = *reinterpret_cast<const float4*>(wr + r * 256 + k);
                acc[r] = fmaf(a0, w.x, acc[r]);
                acc[r] = fmaf(a1, w.y, acc[r]);
                acc[r] = fmaf(a2, w.z, acc[r]);
                acc[r] = fmaf(a3, w.w, acc[r]);
            }
        }
        __syncthreads();
    }
}

// ---------------------------------------------------------------------------
// Kernel: init hidden states (transposed)
// ---------------------------------------------------------------------------
__global__ void init_states_kernel(const float* __restrict__ hs) {
    int idx = blockIdx.x * blockDim.x + threadIdx.x;
    if (idx >= BB * LL * HH) return;
    int b = idx >> 11;
    int l = (idx >> 10) & 1;
    int h = idx & 1023;
    float v = hs[idx];
    if (l == 0) g_h0[0][h * BB + b] = v;
    else        g_h1[0][h * BB + b] = v;
}

// ---------------------------------------------------------------------------
// Big GEMM: layer-0 input projections (3 gates via blockIdx.z)
// ---------------------------------------------------------------------------
__global__ void __launch_bounds__(256) gemm_x0_kernel(
    const float* __restrict__ A,
    const float* __restrict__ Wz, const float* __restrict__ Wr, const float* __restrict__ Wg,
    const float* __restrict__ bz, const float* __restrict__ br, const float* __restrict__ bg)
{
    __shared__ float As[16][68];
    __shared__ float Bs[16][68];
    const int gate = blockIdx.z;
    const float* W    = (gate == 0) ? Wz : (gate == 1) ? Wr : Wg;
    const float* bias = (gate == 0) ? bz : (gate == 1) ? br : bg;
    const int n0 = blockIdx.x * 64;
    const int m0 = blockIdx.y * 64;
    const int tid = threadIdx.x;
    const int lr = tid >> 2;
    const int lk = (tid & 3) * 4;
    const int tm = tid >> 4;
    const int tn = tid & 15;

    float c[4][4] = {};
    for (int k0 = 0; k0 < DD; k0 += 16) {
        float4 av = *reinterpret_cast<const float4*>(A + (size_t)(m0 + lr) * DD + k0 + lk);
        float4 bv = *reinterpret_cast<const float4*>(W + (size_t)(n0 + lr) * DD + k0 + lk);
        As[lk + 0][lr] = av.x; As[lk + 1][lr] = av.y; As[lk + 2][lr] = av.z; As[lk + 3][lr] = av.w;
        Bs[lk + 0][lr] = bv.x; Bs[lk + 1][lr] = bv.y; Bs[lk + 2][lr] = bv.z; Bs[lk + 3][lr] = bv.w;
        __syncthreads();
        #pragma unroll
        for (int k = 0; k < 16; ++k) {
            float a[4], b4[4];
            #pragma unroll
            for (int i = 0; i < 4; ++i) a[i]  = As[k][tm * 4 + i];
            #pragma unroll
            for (int j = 0; j < 4; ++j) b4[j] = Bs[k][tn * 4 + j];
            #pragma unroll
            for (int i = 0; i < 4; ++i)
                #pragma unroll
                for (int j = 0; j < 4; ++j)
                    c[i][j] = fmaf(a[i], b4[j], c[i][j]);
        }
        __syncthreads();
    }
    #pragma unroll
    for (int i = 0; i < 4; ++i) {
        int m = m0 + tm * 4 + i;
        int b = m >> 9;
        int s = m & 511;
        #pragma unroll
        for (int j = 0; j < 4; ++j) {
            int n = n0 + tn * 4 + j;
            g_X0[(((size_t)s * 3 + gate) * HH + n) * BB + b] = c[i][j] + __ldg(&bias[n]);
        }
    }
}

// ---------------------------------------------------------------------------
// Persistent recurrent kernel. 4 phases/step, grid barrier between phases.
// SMEM: sA = 32768 floats (full K x 32 activations), sW = 2 x 8192 floats.
// ---------------------------------------------------------------------------
__global__ void __launch_bounds__(256) gru_recurrent_kernel(
    const float* __restrict__ Whz0, const float* __restrict__ Whr0, const float* __restrict__ Whg0,
    const float* __restrict__ Wxz1, const float* __restrict__ Whz1,
    const float* __restrict__ Wxr1, const float* __restrict__ Whr1,
    const float* __restrict__ Wxg1, const float* __restrict__ Whg1,
    const float* __restrict__ bz1, const float* __restrict__ br1, const float* __restrict__ bg1,
    int nctas)
{
    extern __shared__ float smem[];
    float* sA = smem;              // 32768 floats
    float* sW = smem + 32768;      // 2 x 8192 floats
    const int tid = threadIdx.x;
    const int lane = tid & 31;
    const int wid = tid >> 5;
    const int bid = blockIdx.x;
    const int half = nctas >> 1;

    for (int t = 0; t < SS; ++t) {
        const int par = t & 1;
        const float* __restrict__ h0 = g_h0[par];
        const float* __restrict__ h1 = g_h1[par];
        float* __restrict__ h0n = g_h0[par ^ 1];
        float* __restrict__ h1n = g_h1[par ^ 1];
        const float* __restrict__ X0 = g_X0 + (size_t)t * (3 * HH * BB);
        float acc[4];

        // ---------- P1: z0,r0 (A=h0) | hz1,hr1 (A=h1). 64 tasks/group, 32 rows.
        {
            const bool grp0 = bid < half;
            const int cl = grp0 ? bid : bid - half;
            if (cl < 64) {
                stageA(sA, grp0 ? h0 : h1, tid);
                for (int tt = cl; tt < 64; tt += half) {
                    int gm = tt >> 5, n0 = (tt & 31) << 5;
                    const float* W = grp0 ? (gm ? Whr0 : Whz0) : (gm ? Whr1 : Whz1);
                    gemm_task<32>(sA, sW, W, n0, tid, wid, lane, acc);
                    #pragma unroll
                    for (int r = 0; r < 4; ++r) {
                        int n = n0 + wid * 4 + r, off = (n << 5) + lane;
                        if (grp0) {
                            if (gm == 0) g_z0[off] = sigmoidf_(acc[r] + X0[off]);
                            else         g_r0[off] = sigmoidf_(acc[r] + X0[HH * BB + off]);
                        } else {
                            if (gm == 0) g_hz1[off] = acc[r];
                            else         g_hr1[off] = acc[r];
                        }
                    }
                }
            }
        }
        gridbar(nctas);

        // ---------- P2: g0 = tanh(X0g + Whg0 @ (r0*h0)); h0' update. 64 tasks, 16 rows.
        for (int tt = bid; tt < 64; tt += nctas) {
            if (tt == bid) {  // stage A = r0*h0 (once)
                for (int u = tid; u < 8192; u += 256) {
                    float4 rv = *reinterpret_cast<const float4*>(g_r0 + (u << 2));
                    float4 hv = *reinterpret_cast<const float4*>(h0 + (u << 2));
                    float4 p;
                    p.x = rv.x * hv.x; p.y = rv.y * hv.y; p.z = rv.z * hv.z; p.w = rv.w * hv.w;
                    *reinterpret_cast<float4*>(sA + (u << 2)) = p;
                }
            }
            int n0 = tt << 4;
            gemm_task<16>(sA, sW, Whg0, n0, tid, wid, lane, acc);
            #pragma unroll
            for (int r = 0; r < 2; ++r) {
                int n = n0 + wid * 2 + r, off = (n << 5) + lane;
                float g = tanhf_(acc[r] + X0[2 * HH * BB + off]);
                float z = g_z0[off], hp = h0[off];
                h0n[off] = z * hp + (1.0f - z) * g;
            }
        }
        gridbar(nctas);

        // ---------- P3: xz1,xr1,xg1 on A=h0'. 96 tasks, 32 rows.
        if (bid < 96) {
            stageA(sA, h0n, tid);
            for (int tt = bid; tt < 96; tt += nctas) {
                int gm = tt >> 5, n0 = (tt & 31) << 5;
                const float* W = (gm == 0) ? Wxz1 : (gm == 1) ? Wxr1 : Wxg1;
                gemm_task<32>(sA, sW, W, n0, tid, wid, lane, acc);
                #pragma unroll
                for (int r = 0; r < 4; ++r) {
                    int n = n0 + wid * 4 + r, off = (n << 5) + lane;
                    if (gm == 0)      g_z1[off] = sigmoidf_(acc[r] + g_hz1[off] + bz1[n]);
                    else if (gm == 1) g_r1[off] = sigmoidf_(acc[r] + g_hr1[off] + br1[n]);
                    else              g_pg1[off] = acc[r] + bg1[n];
                }
            }
        }
        gridbar(nctas);

        // ---------- P4: g1 = tanh(pg1 + Whg1 @ (r1*h1)); h1' + Y. 64 tasks, 16 rows.
        for (int tt = bid; tt < 64; tt += nctas) {
            if (tt == bid) {  // stage A = r1*h1
                for (int u = tid; u < 8192; u += 256) {
                    float4 rv = *reinterpret_cast<const float4*>(g_r1 + (u << 2));
                    float4 hv = *reinterpret_cast<const float4*>(h1 + (u << 2));
                    float4 p;
                    p.x = rv.x * hv.x; p.y = rv.y * hv.y; p.z = rv.z * hv.z; p.w = rv.w * hv.w;
                    *reinterpret_cast<float4*>(sA + (u << 2)) = p;
                }
            }
            int n0 = tt << 4;
            gemm_task<16>(sA, sW, Whg1, n0, tid, wid, lane, acc);
            #pragma unroll
            for (int r = 0; r < 2; ++r) {
                int n = n0 + wid * 2 + r, off = (n << 5) + lane;
                float g = tanhf_(acc[r] + g_pg1[off]);
                float z = g_z1[off], hp = h1[off];
                float hn = z * hp + (1.0f - z) * g;
                h1n[off] = hn;
                g_Y[(size_t)t * (HH * BB) + off] = hn;
            }
        }
        gridbar(nctas);
    }
}

// ---------------------------------------------------------------------------
// Output projection out[b][s][o] = Y[s][:,b] . Why[o][:] + by[o]
// ---------------------------------------------------------------------------
__global__ void __launch_bounds__(256) gemm_proj_kernel(
    const float* __restrict__ W, const float* __restrict__ bias, float* __restrict__ out)
{
    __shared__ float As[16][68];
    __shared__ float Bs[16][68];
    const int n0 = blockIdx.x * 64;
    const int m0 = blockIdx.y * 64;
    const int tid = threadIdx.x;
    const int kk = tid >> 4;
    const int m4 = (tid & 15) * 4;
    const int lr = tid >> 2;
    const int lk = (tid & 3) * 4;
    const int tm = tid >> 4;
    const int tn = tid & 15;

    const int mA = m0 + m4;
    const int sA_ = mA >> 5;
    const int bA = mA & 31;

    float c[4][4] = {};
    for (int k0 = 0; k0 < HH; k0 += 16) {
        float4 av = *reinterpret_cast<const float4*>(
            g_Y + (size_t)sA_ * (HH * BB) + (size_t)(k0 + kk) * BB + bA);
        float4 bv = *reinterpret_cast<const float4*>(W + (size_t)(n0 + lr) * HH + k0 + lk);
        As[kk][m4 + 0] = av.x; As[kk][m4 + 1] = av.y; As[kk][m4 + 2] = av.z; As[kk][m4 + 3] = av.w;
        Bs[lk + 0][lr] = bv.x; Bs[lk + 1][lr] = bv.y; Bs[lk + 2][lr] = bv.z; Bs[lk + 3][lr] = bv.w;
        __syncthreads();
        #pragma unroll
        for (int k = 0; k < 16; ++k) {
            float a[4], b4[4];
            #pragma unroll
            for (int i = 0; i < 4; ++i) a[i]  = As[k][tm * 4 + i];
            #pragma unroll
            for (int j = 0; j < 4; ++j) b4[j] = Bs[k][tn * 4 + j];
            #pragma unroll
            for (int i = 0; i < 4; ++i)
                #pragma unroll
                for (int j = 0; j < 4; ++j)
                    c[i][j] = fmaf(a[i], b4[j], c[i][j]);
        }
        __syncthreads();
    }
    #pragma unroll
    for (int i = 0; i < 4; ++i) {
        int m = m0 + tm * 4 + i;
        int s = m >> 5;
        int b = m & 31;
        #pragma unroll
        for (int j = 0; j < 4; ++j) {
            int n = n0 + tn * 4 + j;
            out[(size_t)b * (SS * OO) + (size_t)s * OO + n] = c[i][j] + __ldg(&bias[n]);
        }
    }
}

// ---------------------------------------------------------------------------
// Final hidden states to d_out tail, [b][l][h]
// ---------------------------------------------------------------------------
__global__ void copy_hidden_kernel(float* __restrict__ outh) {
    int idx = blockIdx.x * blockDim.x + threadIdx.x;
    if (idx >= BB * LL * HH) return;
    int b = idx >> 11;
    int l = (idx >> 10) & 1;
    int h = idx & 1023;
    outh[idx] = (l == 0) ? g_h0[0][h * BB + b] : g_h1[0][h * BB + b];
}

// ---------------------------------------------------------------------------
// Launch
// ---------------------------------------------------------------------------
extern "C" void kernel_launch(void* const* d_in, const int* in_sizes, int n_in,
                              void* d_out, int out_size) {
    const float* input  = (const float*)d_in[0];
    const float* hidden = (const float*)d_in[1];
    const float* Wxz = (const float*)d_in[2];
    const float* Whz = (const float*)d_in[3];
    const float* bz  = (const float*)d_in[4];
    const float* Wxr = (const float*)d_in[5];
    const float* Whr = (const float*)d_in[6];
    const float* br  = (const float*)d_in[7];
    const float* Wxg = (const float*)d_in[8];
    const float* Whg = (const float*)d_in[9];
    const float* bg  = (const float*)d_in[10];
    const float* Why = (const float*)d_in[11];
    const float* by  = (const float*)d_in[12];
    float* out = (float*)d_out;

    int dev = 0;
    cudaGetDevice(&dev);
    int nsm = 0;
    cudaDeviceGetAttribute(&nsm, cudaDevAttrMultiProcessorCount, dev);
    if (nsm <= 0) nsm = 148;

    const int SMEM_BYTES = (32768 + 16384) * 4;  // 192 KB
    cudaFuncSetAttribute(gru_recurrent_kernel,
                         cudaFuncAttributeMaxDynamicSharedMemorySize, SMEM_BYTES);

    const size_t WHD  = (size_t)HH * DD;
    const size_t WHHo = (size_t)HH * HH;

    init_states_kernel<<<(BB * LL * HH + 255) / 256, 256>>>(hidden);

    gemm_x0_kernel<<<dim3(HH / 64, (BB * SS) / 64, 3), 256>>>(
        input, Wxz, Wxr, Wxg, bz, br, bg);

    gru_recurrent_kernel<<<nsm, 256, SMEM_BYTES>>>(
        Whz, Whr, Whg,
        Wxz + WHD, Whz + WHHo,
        Wxr + WHD, Whr + WHHo,
        Wxg + WHD, Whg + WHHo,
        bz + HH, br + HH, bg + HH,
        nsm);

    gemm_proj_kernel<<<dim3(OO / 64, (BB * SS) / 64), 256>>>(Why, by, out);

    copy_hidden_kernel<<<(BB * LL * HH + 255) / 256, 256>>>(out + (size_t)BB * SS * OO);
}

// round 6
// speedup vs baseline: 4.6349x; 1.0011x over previous
#include <cuda_runtime.h>
#include <cuda_bf16.h>
#include <cstdint>

// Problem constants
#define BB 32
#define SS 512
#define DD 1024
#define HH 1024
#define OO 1024
#define LL 2

// ---------------------------------------------------------------------------
// Scratch (device globals -- allocation-free per harness rules)
// All per-timestep activations stored TRANSPOSED: [n][b] (b fastest, 32 wide)
// ---------------------------------------------------------------------------
__device__ float g_X0[SS * 3 * HH * BB];   // [t][gate][n][b]  (layer0 x-parts + bias)
__device__ float g_Y [SS * HH * BB];       // [t][n][b]        (layer1 outputs)
__device__ float g_h0[2][HH * BB];         // double-buffered states, [n][b]
__device__ float g_h1[2][HH * BB];
__device__ float g_z0[HH * BB], g_r0[HH * BB];
__device__ float g_hz1[HH * BB], g_hr1[HH * BB];   // layer1 h-part partials
__device__ float g_z1[HH * BB], g_r1[HH * BB], g_pg1[HH * BB];
__device__ unsigned g_bar_count;
__device__ unsigned g_bar_gen;

// ---------------------------------------------------------------------------
// Helpers
// ---------------------------------------------------------------------------
__device__ __forceinline__ float sigmoidf_(float x) {
    return __fdividef(1.0f, 1.0f + __expf(-x));
}
__device__ __forceinline__ float tanhf_(float x) {
    return __fdividef(2.0f, 1.0f + __expf(-2.0f * x)) - 1.0f;
}
__device__ __forceinline__ uint32_t sptr(const void* p) {
    return (uint32_t)__cvta_generic_to_shared(p);
}
#define CP_COMMIT() asm volatile("cp.async.commit_group;")
#define CP_WAIT0()  asm volatile("cp.async.wait_group 0;")
#define CP_WAIT1()  asm volatile("cp.async.wait_group 1;")

// Grid-wide barrier (1 CTA/SM guaranteed by 192KB smem footprint).
__device__ __forceinline__ void gridbar(int nctas) {
    __syncthreads();
    if (threadIdx.x == 0) {
        __threadfence();  // release
        unsigned gen = *(volatile unsigned*)&g_bar_gen;
        unsigned a = atomicAdd(&g_bar_count, 1u);
        if (a == (unsigned)nctas - 1u) {
            g_bar_count = 0u;
            __threadfence();
            atomicAdd(&g_bar_gen, 1u);
        } else {
            while (*(volatile unsigned*)&g_bar_gen == gen) { __nanosleep(32); }
        }
        __threadfence();  // acquire (L1 invalidate)
    }
    __syncthreads();
}

// ---------------------------------------------------------------------------
// cp.async staging
// ---------------------------------------------------------------------------
// Full activation [1024][32] (128 KB) -> sA. Commits its own group.
__device__ __forceinline__ void stageA(float* sA, const float* __restrict__ src, int tid) {
    #pragma unroll
    for (int i = 0; i < 32; ++i) {
        int u = tid + i * 256;
        uint32_t d = sptr(sA + (u << 2));
        asm volatile("cp.async.cg.shared.global [%0], [%1], 16;" :: "r"(d), "l"(src + (u << 2)));
    }
    CP_COMMIT();
}

// Weight chunk: TR rows x 256 K-floats from Wg rows [n0, n0+TR), K-chunk kc.
template<int TR>
__device__ __forceinline__ void issueW(float* dst, const float* __restrict__ Wg,
                                       int n0, int kc, int tid) {
    #pragma unroll
    for (int i = 0; i < TR / 4; ++i) {
        int u = tid + i * 256;            // 16B unit index, TR*64 total
        int row = u >> 6, c16 = u & 63;
        const float* src = Wg + ((size_t)(n0 + row) << 10) + (kc << 8) + (c16 << 2);
        uint32_t d = sptr(dst + (row << 8) + (c16 << 2));
        asm volatile("cp.async.cg.shared.global [%0], [%1], 16;" :: "r"(d), "l"(src));
    }
}

// ---------------------------------------------------------------------------
// One GEMM task: TR rows x 32 batch x K=1024, W streamed via 2-deep pipeline.
// Warp w owns rows [w*G, w*G+G), G = TR/8. acc[r] is per-lane (lane = batch).
// ---------------------------------------------------------------------------
template<int TR>
__device__ __forceinline__ void gemm_task(const float* sA, float* sW,
                                          const float* __restrict__ Wg, int n0,
                                          int tid, int wid, int lane, float* acc) {
    const int G = TR / 8;
    issueW<TR>(sW, Wg, n0, 0, tid);
    CP_COMMIT();
    #pragma unroll
    for (int r = 0; r < G; ++r) acc[r] = 0.0f;

    for (int c = 0; c < 4; ++c) {
        if (c < 3) {
            issueW<TR>(sW + ((c + 1) & 1) * 8192, Wg, n0, c + 1, tid);
            CP_COMMIT();
            CP_WAIT1();
        } else {
            CP_WAIT0();
        }
        __syncthreads();
        const float* Wb = sW + (c & 1) * 8192;
        const float* Ab = sA + (c << 13);            // c*256*32
        const float* wr = Wb + (wid * G) * 256;
        #pragma unroll 2
        for (int k = 0; k < 256; k += 4) {
            float a0 = Ab[((k + 0) << 5) + lane];
            float a1 = Ab[((k + 1) << 5) + lane];
            float a2 = Ab[((k + 2) << 5) + lane];
            float a3 = Ab[((k + 3) << 5) + lane];
            #pragma unroll
            for (int r = 0; r < G; ++r) {
                float4 w = *reinterpret_cast<const float4*>(wr + r * 256 + k);
                acc[r] = fmaf(a0, w.x, acc[r]);
                acc[r] = fmaf(a1, w.y, acc[r]);
                acc[r] = fmaf(a2, w.z, acc[r]);
                acc[r] = fmaf(a3, w.w, acc[r]);
            }
        }
        __syncthreads();
    }
}

// ---------------------------------------------------------------------------
// Kernel: init hidden states (transposed)
// ---------------------------------------------------------------------------
__global__ void init_states_kernel(const float* __restrict__ hs) {
    int idx = blockIdx.x * blockDim.x + threadIdx.x;
    if (idx >= BB * LL * HH) return;
    int b = idx >> 11;
    int l = (idx >> 10) & 1;
    int h = idx & 1023;
    float v = hs[idx];
    if (l == 0) g_h0[0][h * BB + b] = v;
    else        g_h1[0][h * BB + b] = v;
}

// ---------------------------------------------------------------------------
// Big GEMM: layer-0 input projections (3 gates via blockIdx.z)
// ---------------------------------------------------------------------------
__global__ void __launch_bounds__(256) gemm_x0_kernel(
    const float* __restrict__ A,
    const float* __restrict__ Wz, const float* __restrict__ Wr, const float* __restrict__ Wg,
    const float* __restrict__ bz, const float* __restrict__ br, const float* __restrict__ bg)
{
    __shared__ float As[16][68];
    __shared__ float Bs[16][68];
    const int gate = blockIdx.z;
    const float* W    = (gate == 0) ? Wz : (gate == 1) ? Wr : Wg;
    const float* bias = (gate == 0) ? bz : (gate == 1) ? br : bg;
    const int n0 = blockIdx.x * 64;
    const int m0 = blockIdx.y * 64;
    const int tid = threadIdx.x;
    const int lr = tid >> 2;
    const int lk = (tid & 3) * 4;
    const int tm = tid >> 4;
    const int tn = tid & 15;

    float c[4][4] = {};
    for (int k0 = 0; k0 < DD; k0 += 16) {
        float4 av = *reinterpret_cast<const float4*>(A + (size_t)(m0 + lr) * DD + k0 + lk);
        float4 bv = *reinterpret_cast<const float4*>(W + (size_t)(n0 + lr) * DD + k0 + lk);
        As[lk + 0][lr] = av.x; As[lk + 1][lr] = av.y; As[lk + 2][lr] = av.z; As[lk + 3][lr] = av.w;
        Bs[lk + 0][lr] = bv.x; Bs[lk + 1][lr] = bv.y; Bs[lk + 2][lr] = bv.z; Bs[lk + 3][lr] = bv.w;
        __syncthreads();
        #pragma unroll
        for (int k = 0; k < 16; ++k) {
            float a[4], b4[4];
            #pragma unroll
            for (int i = 0; i < 4; ++i) a[i]  = As[k][tm * 4 + i];
            #pragma unroll
            for (int j = 0; j < 4; ++j) b4[j] = Bs[k][tn * 4 + j];
            #pragma unroll
            for (int i = 0; i < 4; ++i)
                #pragma unroll
                for (int j = 0; j < 4; ++j)
                    c[i][j] = fmaf(a[i], b4[j], c[i][j]);
        }
        __syncthreads();
    }
    #pragma unroll
    for (int i = 0; i < 4; ++i) {
        int m = m0 + tm * 4 + i;
        int b = m >> 9;
        int s = m & 511;
        #pragma unroll
        for (int j = 0; j < 4; ++j) {
            int n = n0 + tn * 4 + j;
            g_X0[(((size_t)s * 3 + gate) * HH + n) * BB + b] = c[i][j] + __ldg(&bias[n]);
        }
    }
}

// ---------------------------------------------------------------------------
// Persistent recurrent kernel. 4 phases/step, grid barrier between phases.
// SMEM: sA = 32768 floats (full K x 32 activations), sW = 2 x 8192 floats.
// ---------------------------------------------------------------------------
__global__ void __launch_bounds__(256) gru_recurrent_kernel(
    const float* __restrict__ Whz0, const float* __restrict__ Whr0, const float* __restrict__ Whg0,
    const float* __restrict__ Wxz1, const float* __restrict__ Whz1,
    const float* __restrict__ Wxr1, const float* __restrict__ Whr1,
    const float* __restrict__ Wxg1, const float* __restrict__ Whg1,
    const float* __restrict__ bz1, const float* __restrict__ br1, const float* __restrict__ bg1,
    int nctas)
{
    extern __shared__ float smem[];
    float* sA = smem;              // 32768 floats
    float* sW = smem + 32768;      // 2 x 8192 floats
    const int tid = threadIdx.x;
    const int lane = tid & 31;
    const int wid = tid >> 5;
    const int bid = blockIdx.x;
    const int half = nctas >> 1;

    for (int t = 0; t < SS; ++t) {
        const int par = t & 1;
        const float* __restrict__ h0 = g_h0[par];
        const float* __restrict__ h1 = g_h1[par];
        float* __restrict__ h0n = g_h0[par ^ 1];
        float* __restrict__ h1n = g_h1[par ^ 1];
        const float* __restrict__ X0 = g_X0 + (size_t)t * (3 * HH * BB);
        float acc[4];

        // ---------- P1: z0,r0 (A=h0) | hz1,hr1 (A=h1). 64 tasks/group, 32 rows.
        {
            const bool grp0 = bid < half;
            const int cl = grp0 ? bid : bid - half;
            if (cl < 64) {
                stageA(sA, grp0 ? h0 : h1, tid);
                for (int tt = cl; tt < 64; tt += half) {
                    int gm = tt >> 5, n0 = (tt & 31) << 5;
                    const float* W = grp0 ? (gm ? Whr0 : Whz0) : (gm ? Whr1 : Whz1);
                    gemm_task<32>(sA, sW, W, n0, tid, wid, lane, acc);
                    #pragma unroll
                    for (int r = 0; r < 4; ++r) {
                        int n = n0 + wid * 4 + r, off = (n << 5) + lane;
                        if (grp0) {
                            if (gm == 0) g_z0[off] = sigmoidf_(acc[r] + X0[off]);
                            else         g_r0[off] = sigmoidf_(acc[r] + X0[HH * BB + off]);
                        } else {
                            if (gm == 0) g_hz1[off] = acc[r];
                            else         g_hr1[off] = acc[r];
                        }
                    }
                }
            }
        }
        gridbar(nctas);

        // ---------- P2: g0 = tanh(X0g + Whg0 @ (r0*h0)); h0' update. 64 tasks, 16 rows.
        for (int tt = bid; tt < 64; tt += nctas) {
            if (tt == bid) {  // stage A = r0*h0 (once)
                for (int u = tid; u < 8192; u += 256) {
                    float4 rv = *reinterpret_cast<const float4*>(g_r0 + (u << 2));
                    float4 hv = *reinterpret_cast<const float4*>(h0 + (u << 2));
                    float4 p;
                    p.x = rv.x * hv.x; p.y = rv.y * hv.y; p.z = rv.z * hv.z; p.w = rv.w * hv.w;
                    *reinterpret_cast<float4*>(sA + (u << 2)) = p;
                }
            }
            int n0 = tt << 4;
            gemm_task<16>(sA, sW, Whg0, n0, tid, wid, lane, acc);
            #pragma unroll
            for (int r = 0; r < 2; ++r) {
                int n = n0 + wid * 2 + r, off = (n << 5) + lane;
                float g = tanhf_(acc[r] + X0[2 * HH * BB + off]);
                float z = g_z0[off], hp = h0[off];
                h0n[off] = z * hp + (1.0f - z) * g;
            }
        }
        gridbar(nctas);

        // ---------- P3: xz1,xr1,xg1 on A=h0'. 96 tasks, 32 rows.
        if (bid < 96) {
            stageA(sA, h0n, tid);
            for (int tt = bid; tt < 96; tt += nctas) {
                int gm = tt >> 5, n0 = (tt & 31) << 5;
                const float* W = (gm == 0) ? Wxz1 : (gm == 1) ? Wxr1 : Wxg1;
                gemm_task<32>(sA, sW, W, n0, tid, wid, lane, acc);
                #pragma unroll
                for (int r = 0; r < 4; ++r) {
                    int n = n0 + wid * 4 + r, off = (n << 5) + lane;
                    if (gm == 0)      g_z1[off] = sigmoidf_(acc[r] + g_hz1[off] + bz1[n]);
                    else if (gm == 1) g_r1[off] = sigmoidf_(acc[r] + g_hr1[off] + br1[n]);
                    else              g_pg1[off] = acc[r] + bg1[n];
                }
            }
        }
        gridbar(nctas);

        // ---------- P4: g1 = tanh(pg1 + Whg1 @ (r1*h1)); h1' + Y. 64 tasks, 16 rows.
        for (int tt = bid; tt < 64; tt += nctas) {
            if (tt == bid) {  // stage A = r1*h1
                for (int u = tid; u < 8192; u += 256) {
                    float4 rv = *reinterpret_cast<const float4*>(g_r1 + (u << 2));
                    float4 hv = *reinterpret_cast<const float4*>(h1 + (u << 2));
                    float4 p;
                    p.x = rv.x * hv.x; p.y = rv.y * hv.y; p.z = rv.z * hv.z; p.w = rv.w * hv.w;
                    *reinterpret_cast<float4*>(sA + (u << 2)) = p;
                }
            }
            int n0 = tt << 4;
            gemm_task<16>(sA, sW, Whg1, n0, tid, wid, lane, acc);
            #pragma unroll
            for (int r = 0; r < 2; ++r) {
                int n = n0 + wid * 2 + r, off = (n << 5) + lane;
                float g = tanhf_(acc[r] + g_pg1[off]);
                float z = g_z1[off], hp = h1[off];
                float hn = z * hp + (1.0f - z) * g;
                h1n[off] = hn;
                g_Y[(size_t)t * (HH * BB) + off] = hn;
            }
        }
        gridbar(nctas);
    }
}

// ---------------------------------------------------------------------------
// Output projection out[b][s][o] = Y[s][:,b] . Why[o][:] + by[o]
// ---------------------------------------------------------------------------
__global__ void __launch_bounds__(256) gemm_proj_kernel(
    const float* __restrict__ W, const float* __restrict__ bias, float* __restrict__ out)
{
    __shared__ float As[16][68];
    __shared__ float Bs[16][68];
    const int n0 = blockIdx.x * 64;
    const int m0 = blockIdx.y * 64;
    const int tid = threadIdx.x;
    const int kk = tid >> 4;
    const int m4 = (tid & 15) * 4;
    const int lr = tid >> 2;
    const int lk = (tid & 3) * 4;
    const int tm = tid >> 4;
    const int tn = tid & 15;

    const int mA = m0 + m4;
    const int sA_ = mA >> 5;
    const int bA = mA & 31;

    float c[4][4] = {};
    for (int k0 = 0; k0 < HH; k0 += 16) {
        float4 av = *reinterpret_cast<const float4*>(
            g_Y + (size_t)sA_ * (HH * BB) + (size_t)(k0 + kk) * BB + bA);
        float4 bv = *reinterpret_cast<const float4*>(W + (size_t)(n0 + lr) * HH + k0 + lk);
        As[kk][m4 + 0] = av.x; As[kk][m4 + 1] = av.y; As[kk][m4 + 2] = av.z; As[kk][m4 + 3] = av.w;
        Bs[lk + 0][lr] = bv.x; Bs[lk + 1][lr] = bv.y; Bs[lk + 2][lr] = bv.z; Bs[lk + 3][lr] = bv.w;
        __syncthreads();
        #pragma unroll
        for (int k = 0; k < 16; ++k) {
            float a[4], b4[4];
            #pragma unroll
            for (int i = 0; i < 4; ++i) a[i]  = As[k][tm * 4 + i];
            #pragma unroll
            for (int j = 0; j < 4; ++j) b4[j] = Bs[k][tn * 4 + j];
            #pragma unroll
            for (int i = 0; i < 4; ++i)
                #pragma unroll
                for (int j = 0; j < 4; ++j)
                    c[i][j] = fmaf(a[i], b4[j], c[i][j]);
        }
        __syncthreads();
    }
    #pragma unroll
    for (int i = 0; i < 4; ++i) {
        int m = m0 + tm * 4 + i;
        int s = m >> 5;
        int b = m & 31;
        #pragma unroll
        for (int j = 0; j < 4; ++j) {
            int n = n0 + tn * 4 + j;
            out[(size_t)b * (SS * OO) + (size_t)s * OO + n] = c[i][j] + __ldg(&bias[n]);
        }
    }
}

// ---------------------------------------------------------------------------
// Final hidden states to d_out tail, [b][l][h]
// ---------------------------------------------------------------------------
__global__ void copy_hidden_kernel(float* __restrict__ outh) {
    int idx = blockIdx.x * blockDim.x + threadIdx.x;
    if (idx >= BB * LL * HH) return;
    int b = idx >> 11;
    int l = (idx >> 10) & 1;
    int h = idx & 1023;
    outh[idx] = (l == 0) ? g_h0[0][h * BB + b] : g_h1[0][h * BB + b];
}

// ---------------------------------------------------------------------------
// Launch
// ---------------------------------------------------------------------------
extern "C" void kernel_launch(void* const* d_in, const int* in_sizes, int n_in,
                              void* d_out, int out_size) {
    const float* input  = (const float*)d_in[0];
    const float* hidden = (const float*)d_in[1];
    const float* Wxz = (const float*)d_in[2];
    const float* Whz = (const float*)d_in[3];
    const float* bz  = (const float*)d_in[4];
    const float* Wxr = (const float*)d_in[5];
    const float* Whr = (const float*)d_in[6];
    const float* br  = (const float*)d_in[7];
    const float* Wxg = (const float*)d_in[8];
    const float* Whg = (const float*)d_in[9];
    const float* bg  = (const float*)d_in[10];
    const float* Why = (const float*)d_in[11];
    const float* by  = (const float*)d_in[12];
    float* out = (float*)d_out;

    int dev = 0;
    cudaGetDevice(&dev);
    int nsm = 0;
    cudaDeviceGetAttribute(&nsm, cudaDevAttrMultiProcessorCount, dev);
    if (nsm <= 0) nsm = 148;

    const int SMEM_BYTES = (32768 + 16384) * 4;  // 192 KB
    cudaFuncSetAttribute(gru_recurrent_kernel,
                         cudaFuncAttributeMaxDynamicSharedMemorySize, SMEM_BYTES);

    const size_t WHD  = (size_t)HH * DD;
    const size_t WHHo = (size_t)HH * HH;

    init_states_kernel<<<(BB * LL * HH + 255) / 256, 256>>>(hidden);

    gemm_x0_kernel<<<dim3(HH / 64, (BB * SS) / 64, 3), 256>>>(
        input, Wxz, Wxr, Wxg, bz, br, bg);

    gru_recurrent_kernel<<<nsm, 256, SMEM_BYTES>>>(
        Whz, Whr, Whg,
        Wxz + WHD, Whz + WHHo,
        Wxr + WHD, Whr + WHHo,
        Wxg + WHD, Whg + WHHo,
        bz + HH, br + HH, bg + HH,
        nsm);

    gemm_proj_kernel<<<dim3(OO / 64, (BB * SS) / 64), 256>>>(Why, by, out);

    copy_hidden_kernel<<<(BB * LL * HH + 255) / 256, 256>>>(out + (size_t)BB * SS * OO);
}

// round 8
// speedup vs baseline: 8.9556x; 1.9322x over previous
#include <cuda_runtime.h>
#include <cuda_bf16.h>
#include <cstdint>

// Problem constants
#define BB 32
#define SS 512
#define DD 1024
#define HH 1024
#define OO 1024
#define LL 2
#define HB (HH * BB)   // 32768

// ---------------------------------------------------------------------------
// Scratch (device globals). Activations TRANSPOSED: [n][b], b fastest.
// ---------------------------------------------------------------------------
__device__ float g_X0[SS * 3 * HB];     // [t][gate][n][b]
__device__ float g_Y [SS * HB];         // [t][n][b]
__device__ float g_h0[2][HB];
__device__ float g_h1[2][HB];
__device__ float g_z0[HB];
__device__ float g_rh0[HB];             // r0 * h0 (computed in P1 epilogue)
__device__ float g_hz1[HB], g_hr1[HB];  // layer1 h-part partials
__device__ float g_z1[HB], g_rh1[HB], g_pg1[HB];
// tf32-rounded weights: [0]=Whz0 [1]=Whr0 [2]=Whg0 [3]=Wxz1 [4]=Wxr1 [5]=Wxg1
//                       [6]=Whz1 [7]=Whr1 [8]=Whg1   (1M floats each)
__device__ float g_Wt[9u << 20];
__device__ unsigned g_bar_count;
__device__ unsigned g_bar_gen;

// ---------------------------------------------------------------------------
// Helpers
// ---------------------------------------------------------------------------
__device__ __forceinline__ float sigmoidf_(float x) {
    return __fdividef(1.0f, 1.0f + __expf(-x));
}
__device__ __forceinline__ float tanhf_(float x) {
    return __fdividef(2.0f, 1.0f + __expf(-2.0f * x)) - 1.0f;
}
__device__ __forceinline__ uint32_t sptr(const void* p) {
    return (uint32_t)__cvta_generic_to_shared(p);
}
__device__ __forceinline__ uint32_t to_tf32(float v) {
    uint32_t t;
    asm("cvt.rna.tf32.f32 %0, %1;" : "=r"(t) : "f"(v));
    return t;
}
#define CP_COMMIT() asm volatile("cp.async.commit_group;")
#define CP_WAIT0()  asm volatile("cp.async.wait_group 0;")
#define CP_WAIT1()  asm volatile("cp.async.wait_group 1;")

// Grid-wide barrier (1 CTA/SM guaranteed by 145KB smem footprint).
__device__ __forceinline__ void gridbar(int nctas) {
    __syncthreads();
    if (threadIdx.x == 0) {
        __threadfence();
        unsigned gen = *(volatile unsigned*)&g_bar_gen;
        unsigned a = atomicAdd(&g_bar_count, 1u);
        if (a == (unsigned)nctas - 1u) {
            g_bar_count = 0u;
            __threadfence();
            atomicAdd(&g_bar_gen, 1u);
        } else {
            while (*(volatile unsigned*)&g_bar_gen == gen) { __nanosleep(32); }
        }
        __threadfence();
    }
    __syncthreads();
}

// ---------------------------------------------------------------------------
// SMEM chunk staging (padded conflict-free layouts)
// A chunk: 256 k-rows x 32 b, stride 40.  W chunk: TR rows x 256 k, stride 260.
// ---------------------------------------------------------------------------
#define SA_BUF 10240   // 256*40
#define SW_BUF 8320    // 32*260

__device__ __forceinline__ void stageAchunk(float* buf, const float* __restrict__ src,
                                            int kc, int tid) {
    #pragma unroll
    for (int i = 0; i < 8; ++i) {
        int u = tid + (i << 8);            // 0..2047 (16B units)
        int k = u >> 3, c4 = (u & 7) << 2;
        uint32_t d = sptr(buf + k * 40 + c4);
        asm volatile("cp.async.cg.shared.global [%0], [%1], 16;"
                     :: "r"(d), "l"(src + (kc << 13) + (k << 5) + c4));
    }
}

template<int TR>
__device__ __forceinline__ void stageWchunk(float* buf, const float* __restrict__ Wt,
                                            int n0, int kc, int tid) {
    #pragma unroll
    for (int i = 0; i < TR / 4; ++i) {
        int u = tid + (i << 8);            // TR*64 16B units
        int row = u >> 6, c16 = (u & 63) << 2;
        uint32_t d = sptr(buf + row * 260 + c16);
        asm volatile("cp.async.cg.shared.global [%0], [%1], 16;"
                     :: "r"(d), "l"(Wt + ((size_t)(n0 + row) << 10) + (kc << 8) + c16));
    }
}

// ---------------------------------------------------------------------------
// tf32 tensor-core GEMM task: TR rows x 32 batch x K=1024.
// Warp = (m-tile, n-tile): 16 n-rows x 8 batch per warp, acc[4] fp32.
// TR=32: 8 warps (2x4). TR=16: warps 0..3 compute (1x4); all warps stage.
// ---------------------------------------------------------------------------
template<int TR>
__device__ __forceinline__ void gemm_task_tc(const float* __restrict__ srcA,
                                             const float* __restrict__ Wt, int n0,
                                             float* sA, float* sW,
                                             int tid, int wid, int lane, float* acc) {
    acc[0] = acc[1] = acc[2] = acc[3] = 0.0f;
    stageAchunk(sA, srcA, 0, tid);
    stageWchunk<TR>(sW, Wt, n0, 0, tid);
    CP_COMMIT();
    const int mt = (TR == 32) ? (wid >> 2) : 0;
    const int nt = wid & 3;
    const bool active = (TR == 32) || (wid < 4);
    const int gid = lane >> 2, tig = lane & 3;

    for (int c = 0; c < 4; ++c) {
        if (c < 3) {
            stageAchunk(sA + ((c + 1) & 1) * SA_BUF, srcA, c + 1, tid);
            stageWchunk<TR>(sW + ((c + 1) & 1) * SW_BUF, Wt, n0, c + 1, tid);
            CP_COMMIT();
            CP_WAIT1();
        } else {
            CP_WAIT0();
        }
        __syncthreads();
        if (active) {
            const float* Ab = sA + (c & 1) * SA_BUF + nt * 8 + gid;
            const float* Wb = sW + (c & 1) * SW_BUF + (mt * 16 + gid) * 260 + tig;
            #pragma unroll 4
            for (int kk = 0; kk < 32; ++kk) {
                int k8 = kk << 3;
                uint32_t a0 = __float_as_uint(Wb[k8]);
                uint32_t a1 = __float_as_uint(Wb[8 * 260 + k8]);
                uint32_t a2 = __float_as_uint(Wb[k8 + 4]);
                uint32_t a3 = __float_as_uint(Wb[8 * 260 + k8 + 4]);
                uint32_t b0 = to_tf32(Ab[(k8 + tig) * 40]);
                uint32_t b1 = to_tf32(Ab[(k8 + tig + 4) * 40]);
                asm volatile(
                    "mma.sync.aligned.m16n8k8.row.col.f32.tf32.tf32.f32 "
                    "{%0,%1,%2,%3}, {%4,%5,%6,%7}, {%8,%9}, {%0,%1,%2,%3};"
                    : "+f"(acc[0]), "+f"(acc[1]), "+f"(acc[2]), "+f"(acc[3])
                    : "r"(a0), "r"(a1), "r"(a2), "r"(a3), "r"(b0), "r"(b1));
            }
        }
        __syncthreads();
    }
}

// ---------------------------------------------------------------------------
// Kernel: one-time tf32 rounding of the 9 recurrent-path weight matrices
// ---------------------------------------------------------------------------
__global__ void __launch_bounds__(256) convert_w_kernel(
    const float* __restrict__ w0, const float* __restrict__ w1,
    const float* __restrict__ w2, const float* __restrict__ w3,
    const float* __restrict__ w4, const float* __restrict__ w5,
    const float* __restrict__ w6, const float* __restrict__ w7,
    const float* __restrict__ w8)
{
    unsigned i = blockIdx.x * 256u + threadIdx.x;   // grid covers exactly 9M
    unsigned m = i >> 20, r = i & ((1u << 20) - 1);
    const float* s;
    switch (m) {
        case 0: s = w0; break; case 1: s = w1; break; case 2: s = w2; break;
        case 3: s = w3; break; case 4: s = w4; break; case 5: s = w5; break;
        case 6: s = w6; break; case 7: s = w7; break; default: s = w8; break;
    }
    g_Wt[i] = __uint_as_float(to_tf32(s[r]));
}

// ---------------------------------------------------------------------------
// Kernel: init hidden states (transposed)
// ---------------------------------------------------------------------------
__global__ void init_states_kernel(const float* __restrict__ hs) {
    int idx = blockIdx.x * blockDim.x + threadIdx.x;
    if (idx >= BB * LL * HH) return;
    int b = idx >> 11;
    int l = (idx >> 10) & 1;
    int h = idx & 1023;
    float v = hs[idx];
    if (l == 0) g_h0[0][h * BB + b] = v;
    else        g_h1[0][h * BB + b] = v;
}

// ---------------------------------------------------------------------------
// Big GEMM: layer-0 input projections (3 gates via blockIdx.z), exact fp32
// ---------------------------------------------------------------------------
__global__ void __launch_bounds__(256) gemm_x0_kernel(
    const float* __restrict__ A,
    const float* __restrict__ Wz, const float* __restrict__ Wr, const float* __restrict__ Wg,
    const float* __restrict__ bz, const float* __restrict__ br, const float* __restrict__ bg)
{
    __shared__ float As[16][68];
    __shared__ float Bs[16][68];
    const int gate = blockIdx.z;
    const float* W    = (gate == 0) ? Wz : (gate == 1) ? Wr : Wg;
    const float* bias = (gate == 0) ? bz : (gate == 1) ? br : bg;
    const int n0 = blockIdx.x * 64;
    const int m0 = blockIdx.y * 64;
    const int tid = threadIdx.x;
    const int lr = tid >> 2;
    const int lk = (tid & 3) * 4;
    const int tm = tid >> 4;
    const int tn = tid & 15;

    float c[4][4] = {};
    for (int k0 = 0; k0 < DD; k0 += 16) {
        float4 av = *reinterpret_cast<const float4*>(A + (size_t)(m0 + lr) * DD + k0 + lk);
        float4 bv = *reinterpret_cast<const float4*>(W + (size_t)(n0 + lr) * DD + k0 + lk);
        As[lk + 0][lr] = av.x; As[lk + 1][lr] = av.y; As[lk + 2][lr] = av.z; As[lk + 3][lr] = av.w;
        Bs[lk + 0][lr] = bv.x; Bs[lk + 1][lr] = bv.y; Bs[lk + 2][lr] = bv.z; Bs[lk + 3][lr] = bv.w;
        __syncthreads();
        #pragma unroll
        for (int k = 0; k < 16; ++k) {
            float a[4], b4[4];
            #pragma unroll
            for (int i = 0; i < 4; ++i) a[i]  = As[k][tm * 4 + i];
            #pragma unroll
            for (int j = 0; j < 4; ++j) b4[j] = Bs[k][tn * 4 + j];
            #pragma unroll
            for (int i = 0; i < 4; ++i)
                #pragma unroll
                for (int j = 0; j < 4; ++j)
                    c[i][j] = fmaf(a[i], b4[j], c[i][j]);
        }
        __syncthreads();
    }
    #pragma unroll
    for (int i = 0; i < 4; ++i) {
        int m = m0 + tm * 4 + i;
        int b = m >> 9;
        int s = m & 511;
        #pragma unroll
        for (int j = 0; j < 4; ++j) {
            int n = n0 + tn * 4 + j;
            g_X0[(((size_t)s * 3 + gate) * HH + n) * BB + b] = c[i][j] + __ldg(&bias[n]);
        }
    }
}

// ---------------------------------------------------------------------------
// Persistent recurrent kernel (tf32 TC). 4 phases/step + gridbar each.
// SMEM: sA 2x10240 floats, sW 2x8320 floats = 145 KB.
// ---------------------------------------------------------------------------
__global__ void __launch_bounds__(256) gru_recurrent_kernel(
    const float* __restrict__ bz1, const float* __restrict__ br1,
    const float* __restrict__ bg1, int nctas)
{
    extern __shared__ float smem[];
    float* sA = smem;              // 2 x SA_BUF
    float* sW = smem + 2 * SA_BUF; // 2 x SW_BUF
    const int tid = threadIdx.x;
    const int lane = tid & 31;
    const int wid = tid >> 5;
    const int bid = blockIdx.x;
    const int gid = lane >> 2, tig = lane & 3;
    float acc[4];

    for (int t = 0; t < SS; ++t) {
        const int par = t & 1;
        const float* __restrict__ h0 = g_h0[par];
        const float* __restrict__ h1 = g_h1[par];
        float* __restrict__ h0n = g_h0[par ^ 1];
        float* __restrict__ h1n = g_h1[par ^ 1];
        const float* __restrict__ X0 = g_X0 + (size_t)t * (3 * HB);

        // ---- P1: z0,r0 (A=h0, W=Whz0/Whr0) | hz1,hr1 (A=h1, W=Whz1/Whr1).
        for (int tt = bid; tt < 128; tt += nctas) {
            int gm = tt >> 5, n0 = (tt & 31) << 5;
            const float* A = (gm < 2) ? h0 : h1;
            const float* W = g_Wt + ((size_t)((gm == 0) ? 0 : (gm == 1) ? 1 :
                                              (gm == 2) ? 6 : 7) << 20);
            gemm_task_tc<32>(A, W, n0, sA, sW, tid, wid, lane, acc);
            int mt = wid >> 2, nt = wid & 3;
            #pragma unroll
            for (int e = 0; e < 4; ++e) {
                int n = n0 + mt * 16 + gid + ((e >> 1) << 3);
                int off = (n << 5) + nt * 8 + tig * 2 + (e & 1);
                if (gm == 0)      g_z0[off] = sigmoidf_(acc[e] + X0[off]);
                else if (gm == 1) {
                    float r = sigmoidf_(acc[e] + X0[HB + off]);
                    g_rh0[off] = r * h0[off];
                } else if (gm == 2) g_hz1[off] = acc[e];
                else                g_hr1[off] = acc[e];
            }
        }
        gridbar(nctas);

        // ---- P2: g0 = tanh(X0g + Whg0 @ rh0); h0' update. 64 tasks TR=16.
        for (int tt = bid; tt < 64; tt += nctas) {
            int n0 = tt << 4;
            gemm_task_tc<16>(g_rh0, g_Wt + ((size_t)2 << 20), n0, sA, sW, tid, wid, lane, acc);
            if (wid < 4) {
                int nt = wid;
                #pragma unroll
                for (int e = 0; e < 4; ++e) {
                    int n = n0 + gid + ((e >> 1) << 3);
                    int off = (n << 5) + nt * 8 + tig * 2 + (e & 1);
                    float g = tanhf_(acc[e] + X0[2 * HB + off]);
                    float z = g_z0[off], hp = h0[off];
                    h0n[off] = z * hp + (1.0f - z) * g;
                }
            }
        }
        gridbar(nctas);

        // ---- P3: xz1,xr1,xg1 on A=h0'. 96 tasks TR=32.
        for (int tt = bid; tt < 96; tt += nctas) {
            int gm = tt >> 5, n0 = (tt & 31) << 5;
            const float* W = g_Wt + ((size_t)(3 + gm) << 20);
            gemm_task_tc<32>(h0n, W, n0, sA, sW, tid, wid, lane, acc);
            int mt = wid >> 2, nt = wid & 3;
            #pragma unroll
            for (int e = 0; e < 4; ++e) {
                int n = n0 + mt * 16 + gid + ((e >> 1) << 3);
                int off = (n << 5) + nt * 8 + tig * 2 + (e & 1);
                if (gm == 0)      g_z1[off] = sigmoidf_(acc[e] + g_hz1[off] + bz1[n]);
                else if (gm == 1) {
                    float r = sigmoidf_(acc[e] + g_hr1[off] + br1[n]);
                    g_rh1[off] = r * h1[off];
                } else            g_pg1[off] = acc[e] + bg1[n];
            }
        }
        gridbar(nctas);

        // ---- P4: g1 = tanh(pg1 + Whg1 @ rh1); h1' + Y. 64 tasks TR=16.
        for (int tt = bid; tt < 64; tt += nctas) {
            int n0 = tt << 4;
            gemm_task_tc<16>(g_rh1, g_Wt + ((size_t)8 << 20), n0, sA, sW, tid, wid, lane, acc);
            if (wid < 4) {
                int nt = wid;
                #pragma unroll
                for (int e = 0; e < 4; ++e) {
                    int n = n0 + gid + ((e >> 1) << 3);
                    int off = (n << 5) + nt * 8 + tig * 2 + (e & 1);
                    float g = tanhf_(acc[e] + g_pg1[off]);
                    float z = g_z1[off], hp = h1[off];
                    float hn = z * hp + (1.0f - z) * g;
                    h1n[off] = hn;
                    g_Y[(size_t)t * HB + off] = hn;
                }
            }
        }
        gridbar(nctas);
    }
}

// ---------------------------------------------------------------------------
// Output projection out[b][s][o] = Y[s][:,b] . Why[o][:] + by[o], exact fp32
// ---------------------------------------------------------------------------
__global__ void __launch_bounds__(256) gemm_proj_kernel(
    const float* __restrict__ W, const float* __restrict__ bias, float* __restrict__ out)
{
    __shared__ float As[16][68];
    __shared__ float Bs[16][68];
    const int n0 = blockIdx.x * 64;
    const int m0 = blockIdx.y * 64;
    const int tid = threadIdx.x;
    const int kk = tid >> 4;
    const int m4 = (tid & 15) * 4;
    const int lr = tid >> 2;
    const int lk = (tid & 3) * 4;
    const int tm = tid >> 4;
    const int tn = tid & 15;

    const int mA = m0 + m4;
    const int sA_ = mA >> 5;
    const int bA = mA & 31;

    float c[4][4] = {};
    for (int k0 = 0; k0 < HH; k0 += 16) {
        float4 av = *reinterpret_cast<const float4*>(
            g_Y + (size_t)sA_ * HB + (size_t)(k0 + kk) * BB + bA);
        float4 bv = *reinterpret_cast<const float4*>(W + (size_t)(n0 + lr) * HH + k0 + lk);
        As[kk][m4 + 0] = av.x; As[kk][m4 + 1] = av.y; As[kk][m4 + 2] = av.z; As[kk][m4 + 3] = av.w;
        Bs[lk + 0][lr] = bv.x; Bs[lk + 1][lr] = bv.y; Bs[lk + 2][lr] = bv.z; Bs[lk + 3][lr] = bv.w;
        __syncthreads();
        #pragma unroll
        for (int k = 0; k < 16; ++k) {
            float a[4], b4[4];
            #pragma unroll
            for (int i = 0; i < 4; ++i) a[i]  = As[k][tm * 4 + i];
            #pragma unroll
            for (int j = 0; j < 4; ++j) b4[j] = Bs[k][tn * 4 + j];
            #pragma unroll
            for (int i = 0; i < 4; ++i)
                #pragma unroll
                for (int j = 0; j < 4; ++j)
                    c[i][j] = fmaf(a[i], b4[j], c[i][j]);
        }
        __syncthreads();
    }
    #pragma unroll
    for (int i = 0; i < 4; ++i) {
        int m = m0 + tm * 4 + i;
        int s = m >> 5;
        int b = m & 31;
        #pragma unroll
        for (int j = 0; j < 4; ++j) {
            int n = n0 + tn * 4 + j;
            out[(size_t)b * (SS * OO) + (size_t)s * OO + n] = c[i][j] + __ldg(&bias[n]);
        }
    }
}

// ---------------------------------------------------------------------------
// Final hidden states to d_out tail, [b][l][h]
// ---------------------------------------------------------------------------
__global__ void copy_hidden_kernel(float* __restrict__ outh) {
    int idx = blockIdx.x * blockDim.x + threadIdx.x;
    if (idx >= BB * LL * HH) return;
    int b = idx >> 11;
    int l = (idx >> 10) & 1;
    int h = idx & 1023;
    outh[idx] = (l == 0) ? g_h0[0][h * BB + b] : g_h1[0][h * BB + b];
}

// ---------------------------------------------------------------------------
// Launch
// ---------------------------------------------------------------------------
extern "C" void kernel_launch(void* const* d_in, const int* in_sizes, int n_in,
                              void* d_out, int out_size) {
    const float* input  = (const float*)d_in[0];
    const float* hidden = (const float*)d_in[1];
    const float* Wxz = (const float*)d_in[2];
    const float* Whz = (const float*)d_in[3];
    const float* bz  = (const float*)d_in[4];
    const float* Wxr = (const float*)d_in[5];
    const float* Whr = (const float*)d_in[6];
    const float* br  = (const float*)d_in[7];
    const float* Wxg = (const float*)d_in[8];
    const float* Whg = (const float*)d_in[9];
    const float* bg  = (const float*)d_in[10];
    const float* Why = (const float*)d_in[11];
    const float* by  = (const float*)d_in[12];
    float* out = (float*)d_out;

    int dev = 0;
    cudaGetDevice(&dev);
    int nsm = 0;
    cudaDeviceGetAttribute(&nsm, cudaDevAttrMultiProcessorCount, dev);
    if (nsm <= 0) nsm = 148;

    const int SMEM_BYTES = (2 * SA_BUF + 2 * SW_BUF) * 4;  // 148480 B
    cudaFuncSetAttribute(gru_recurrent_kernel,
                         cudaFuncAttributeMaxDynamicSharedMemorySize, SMEM_BYTES);

    const size_t WHD  = (size_t)HH * DD;
    const size_t WHHo = (size_t)HH * HH;

    // tf32-round the 9 recurrent-path weight matrices (order matches g_Wt map)
    convert_w_kernel<<<(9u << 20) / 256, 256>>>(
        Whz, Whr, Whg,                       // Whz0, Whr0, Whg0
        Wxz + WHD, Wxr + WHD, Wxg + WHD,     // Wxz1, Wxr1, Wxg1
        Whz + WHHo, Whr + WHHo, Whg + WHHo); // Whz1, Whr1, Whg1

    init_states_kernel<<<(BB * LL * HH + 255) / 256, 256>>>(hidden);

    gemm_x0_kernel<<<dim3(HH / 64, (BB * SS) / 64, 3), 256>>>(
        input, Wxz, Wxr, Wxg, bz, br, bg);

    gru_recurrent_kernel<<<nsm, 256, SMEM_BYTES>>>(
        bz + HH, br + HH, bg + HH, nsm);

    gemm_proj_kernel<<<dim3(OO / 64, (BB * SS) / 64), 256>>>(Why, by, out);

    copy_hidden_kernel<<<(BB * LL * HH + 255) / 256, 256>>>(out + (size_t)BB * SS * OO);
}